// round 1
// baseline (speedup 1.0000x reference)
#include <cuda_runtime.h>

// HamiltonianFlow: 100 RK4 steps of a Hamiltonian MLP vector field.
// 256 independent samples -> 128 CTAs x 2 samples, zero inter-CTA comm.
// W1 rows [0,220) cached fp32 in SMEM (stride 257: conflict-free row AND
// column access). Rows [220,256): forward contributions register-cached
// per thread; backward contributions via warp-cooperative coalesced LDG.

#define FEAT   256
#define HID    256
#define NSAMP  256
#define STEPS  100
#define DTV    0.01f
#define SR     220          // W1 rows resident in SMEM
#define G      36           // remaining rows (FEAT - SR)
#define WST    257          // SMEM row stride (conflict-free both ways)
#define NT     256          // threads per CTA
#define BPC    2            // samples per CTA
#define NCTA   (NSAMP / BPC)

#define SMEM_FLOATS (SR * WST + 512 + 512 + 2 * G)
#define SMEM_BYTES  (SMEM_FLOATS * 4)

__device__ __forceinline__ float warp_sum(float v) {
    v += __shfl_xor_sync(0xffffffffu, v, 16);
    v += __shfl_xor_sync(0xffffffffu, v, 8);
    v += __shfl_xor_sync(0xffffffffu, v, 4);
    v += __shfl_xor_sync(0xffffffffu, v, 2);
    v += __shfl_xor_sync(0xffffffffu, v, 1);
    return v;
}

__global__ __launch_bounds__(NT, 1)
void hflow_kernel(const float* __restrict__ x0,
                  const float* __restrict__ W1,
                  const float* __restrict__ b1,
                  const float* __restrict__ W2,
                  float* __restrict__ out)
{
    extern __shared__ float sm[];
    float* ws   = sm;                    // [SR][WST]
    float* qbuf = sm + SR * WST;         // [2][256]
    float* ubuf = qbuf + 512;            // [2][256]
    float* fbuf = ubuf + 512;            // [2][G]

    const int t    = threadIdx.x;
    const int lane = t & 31;
    const int wid  = t >> 5;

    // ---- one-time per-launch setup (deterministic every call) ----
    for (int idx = t; idx < SR * 256; idx += NT) {
        int f = idx >> 8, j = idx & 255;
        ws[f * WST + j] = W1[idx];
    }
    float wreg[G];                       // forward weights for rows >= SR
#pragma unroll
    for (int i = 0; i < G; i++) wreg[i] = W1[(SR + i) * 256 + t];

    const float rb1 = b1[t];
    const float rw2 = W2[t];

    const int s0 = blockIdx.x * BPC;
    float2 st0 = ((const float2*)x0)[s0 * 256 + t];
    float2 st1 = ((const float2*)x0)[(s0 + 1) * 256 + t];
    float q0 = st0.x, p0 = st0.y;
    float q1 = st1.x, p1 = st1.y;

    const float* wrow = ws + t * WST;    // row t of W1 (valid when t < SR)
    const float h2 = 0.5f * DTV;

    float F0, F1;

    // FORCE: given stage q in (sq0, sq1), compute F = dV/dq into (F0, F1).
    auto FORCE = [&](float sq0v, float sq1v) {
        qbuf[t]       = sq0v;
        qbuf[256 + t] = sq1v;
        __syncthreads();                                  // A: qbuf ready
        // ---- forward matvec: z_j = sum_f q_f * W1[f][j] ----
        float za = 0.f, zb = 0.f, zc = 0.f, zd = 0.f;
#pragma unroll 5
        for (int f = 0; f < SR; f += 4) {
            float4 qa = *(const float4*)&qbuf[f];
            float4 qc = *(const float4*)&qbuf[256 + f];
            float w0 = ws[(f + 0) * WST + t];
            float w1 = ws[(f + 1) * WST + t];
            float w2 = ws[(f + 2) * WST + t];
            float w3 = ws[(f + 3) * WST + t];
            za += w0 * qa.x; zc += w0 * qc.x;
            zb += w1 * qa.y; zd += w1 * qc.y;
            za += w2 * qa.z; zc += w2 * qc.z;
            zb += w3 * qa.w; zd += w3 * qc.w;
        }
#pragma unroll
        for (int i = 0; i < G; i += 4) {
            float4 qa = *(const float4*)&qbuf[SR + i];
            float4 qc = *(const float4*)&qbuf[256 + SR + i];
            za += wreg[i + 0] * qa.x; zc += wreg[i + 0] * qc.x;
            zb += wreg[i + 1] * qa.y; zd += wreg[i + 1] * qc.y;
            za += wreg[i + 2] * qa.z; zc += wreg[i + 2] * qc.z;
            zb += wreg[i + 3] * qa.w; zd += wreg[i + 3] * qc.w;
        }
        {
            float z0 = za + zb + rb1;
            float z1 = zc + zd + rb1;
            // tanh via exp: accurate ~1e-7, flag-independent
            float e0 = __expf(2.f * z0);
            float e1 = __expf(2.f * z1);
            float th0 = 1.f - 2.f / (e0 + 1.f);
            float th1 = 1.f - 2.f / (e1 + 1.f);
            ubuf[t]       = rw2 * (1.f - th0 * th0);
            ubuf[256 + t] = rw2 * (1.f - th1 * th1);
        }
        __syncthreads();                                  // B: ubuf ready
        // ---- backward matvec: F_f = sum_j W1[f][j] * u_j ----
        float Fa = 0.f, Fb = 0.f, Fc = 0.f, Fd = 0.f;
        if (t < SR) {
#pragma unroll 4
            for (int j = 0; j < 256; j += 4) {
                float4 u0 = *(const float4*)&ubuf[j];
                float4 u1 = *(const float4*)&ubuf[256 + j];
                float w0 = wrow[j + 0];
                float w1 = wrow[j + 1];
                float w2 = wrow[j + 2];
                float w3 = wrow[j + 3];
                Fa += w0 * u0.x; Fc += w0 * u1.x;
                Fb += w1 * u0.y; Fd += w1 * u1.y;
                Fa += w2 * u0.z; Fc += w2 * u1.z;
                Fb += w3 * u0.w; Fd += w3 * u1.w;
            }
        }
        // ---- rows [SR,256): warp-cooperative dot products (coalesced LDG) ----
        {
            float4 ua0 = *(const float4*)&ubuf[8 * lane];
            float4 ua1 = *(const float4*)&ubuf[8 * lane + 4];
            float4 ub0 = *(const float4*)&ubuf[256 + 8 * lane];
            float4 ub1 = *(const float4*)&ubuf[256 + 8 * lane + 4];
            for (int i = wid; i < G; i += 8) {
                const float4* wr = (const float4*)(W1 + (SR + i) * 256);
                float4 wa = __ldg(&wr[2 * lane]);
                float4 wb = __ldg(&wr[2 * lane + 1]);
                float v0 = wa.x * ua0.x + wa.y * ua0.y + wa.z * ua0.z + wa.w * ua0.w
                         + wb.x * ua1.x + wb.y * ua1.y + wb.z * ua1.z + wb.w * ua1.w;
                float v1 = wa.x * ub0.x + wa.y * ub0.y + wa.z * ub0.z + wa.w * ub0.w
                         + wb.x * ub1.x + wb.y * ub1.y + wb.z * ub1.z + wb.w * ub1.w;
                v0 = warp_sum(v0);
                v1 = warp_sum(v1);
                if (lane == 0) { fbuf[i] = v0; fbuf[G + i] = v1; }
            }
        }
        __syncthreads();                                  // C: fbuf ready
        if (t >= SR) {
            Fa = fbuf[t - SR];
            Fc = fbuf[G + (t - SR)];
            Fb = 0.f; Fd = 0.f;
        }
        F0 = Fa + Fb;
        F1 = Fc + Fd;
    };

    // ---- time integration ----
    for (int step = 0; step < STEPS; step++) {
        float aq0 = 0.f, ap0 = 0.f, aq1 = 0.f, ap1 = 0.f;
        float sq0 = q0, sp0 = p0, sq1 = q1, sp1 = p1;
        for (int stage = 0; stage < 4; stage++) {
            FORCE(sq0, sq1);
            float wk = (stage == 0 || stage == 3) ? 1.f : 2.f;
            aq0 += wk * sp0; ap0 -= wk * F0;
            aq1 += wk * sp1; ap1 -= wk * F1;
            if (stage < 3) {
                float c = (stage == 2) ? DTV : h2;
                float nsq0 = q0 + c * sp0, nsp0 = p0 - c * F0;
                float nsq1 = q1 + c * sp1, nsp1 = p1 - c * F1;
                sq0 = nsq0; sp0 = nsp0;
                sq1 = nsq1; sp1 = nsp1;
            }
        }
        const float d6 = DTV / 6.f;
        q0 += d6 * aq0; p0 += d6 * ap0;
        q1 += d6 * aq1; p1 += d6 * ap1;
    }

    ((float2*)out)[s0 * 256 + t]       = make_float2(q0, p0);
    ((float2*)out)[(s0 + 1) * 256 + t] = make_float2(q1, p1);
}

extern "C" void kernel_launch(void* const* d_in, const int* in_sizes, int n_in,
                              void* d_out, int out_size) {
    const float* x0 = (const float*)d_in[0];
    const float* W1 = (const float*)d_in[1];
    const float* b1 = (const float*)d_in[2];
    const float* W2 = (const float*)d_in[3];
    // b2 (d_in[4]) does not affect the gradient flow.
    cudaFuncSetAttribute(hflow_kernel,
                         cudaFuncAttributeMaxDynamicSharedMemorySize, SMEM_BYTES);
    hflow_kernel<<<NCTA, NT, SMEM_BYTES>>>(x0, W1, b1, W2, (float*)d_out);
}

// round 2
// speedup vs baseline: 1.0929x; 1.0929x over previous
#include <cuda_runtime.h>

// HamiltonianFlow: 100 RK4 steps (400 sequential MLP-gradient evals).
// 256 independent samples -> 128 CTAs x 2 samples, zero inter-CTA comm.
//
// W1 stored TRANSPOSED in SMEM: wsT[j][f] = W1[f][j], j in [0,256), f in [0,220).
//  - forward (z_j = sum_f q_f W[f][j]): thread t reads row t of wsT contiguously
//    -> LDS.128 (4-phase data minimum) feeding packed fma.rn.f32x2.
//  - backward (F_f = sum_j W[f][j] u_j): thread t reads column t of wsT
//    (all lanes same j, distinct t -> conflict-free scalar, 1-phase minimum).
//    j in [0,128) register-cached as packed b64 pairs -> FFMA2, no smem.
// f in [220,256): forward from per-thread regs; backward rows via L2 LDG + warp reduce.

#define STEPS  100
#define DTV    0.01f
#define SRF    220           // f-columns of wsT resident in SMEM
#define G      36            // 256 - SRF
#define RB     128           // backward j range cached in registers
#define NT     256
#define NCTA   128

typedef unsigned long long ull;

#define WS_FLOATS (256 * SRF)
#define SMEM_BYTES ((WS_FLOATS + 4 * 256 + 128) * 4)

__device__ __forceinline__ void fma2(ull& d, ull a, ull b) {
    asm("fma.rn.f32x2 %0, %1, %2, %0;" : "+l"(d) : "l"(a), "l"(b));
}
__device__ __forceinline__ ull pk2(float lo, float hi) {
    return (ull)__float_as_uint(lo) | ((ull)__float_as_uint(hi) << 32);
}
__device__ __forceinline__ float psum(ull v) {
    return __uint_as_float((unsigned)(v & 0xffffffffu)) +
           __uint_as_float((unsigned)(v >> 32));
}
__device__ __forceinline__ float warp_sum(float v) {
    v += __shfl_xor_sync(0xffffffffu, v, 16);
    v += __shfl_xor_sync(0xffffffffu, v, 8);
    v += __shfl_xor_sync(0xffffffffu, v, 4);
    v += __shfl_xor_sync(0xffffffffu, v, 2);
    v += __shfl_xor_sync(0xffffffffu, v, 1);
    return v;
}
__device__ __forceinline__ float dot4(float4 a, float4 b) {
    return a.x * b.x + a.y * b.y + a.z * b.z + a.w * b.w;
}

__global__ __launch_bounds__(NT, 1)
void hflow_kernel(const float* __restrict__ x0,
                  const float* __restrict__ W1,
                  const float* __restrict__ b1,
                  const float* __restrict__ W2,
                  float* __restrict__ out)
{
    extern __shared__ float sm[];
    float* wsT  = sm;                       // [256][SRF]
    float* qb0  = sm + WS_FLOATS;           // [256]
    float* qb1  = qb0 + 256;
    float* ub0  = qb1 + 256;
    float* ub1  = ub0 + 256;
    float* fb0  = ub1 + 256;                // [G]
    float* fb1  = fb0 + 64;

    const int t    = threadIdx.x;
    const int lane = t & 31;
    const int wid  = t >> 5;

    // ---- stage wsT (transposed) from gmem ----
    for (int idx = t; idx < SRF * 256; idx += NT) {
        int f = idx >> 8, j = idx & 255;
        wsT[j * SRF + f] = W1[idx];          // coalesced read
    }
    // forward weights for f in [SRF,256): packed pairs
    ull wg[G / 2];
#pragma unroll
    for (int k = 0; k < G / 2; k++)
        wg[k] = pk2(W1[(SRF + 2 * k) * 256 + t], W1[(SRF + 2 * k + 1) * 256 + t]);

    const float rb1 = b1[t];
    const float rw2 = W2[t];

    const int s0 = blockIdx.x * 2;
    float2 st0 = ((const float2*)x0)[s0 * 256 + t];
    float2 st1 = ((const float2*)x0)[(s0 + 1) * 256 + t];
    float q0 = st0.x, p0 = st0.y;
    float q1 = st1.x, p1 = st1.y;

    __syncthreads();                         // wsT staged

    // ---- register-cache backward row t, j in [0,RB), as packed pairs ----
    ull rc[RB / 2];
    if (t < SRF) {
#pragma unroll
        for (int k = 0; k < RB / 2; k++)
            rc[k] = pk2(wsT[(2 * k) * SRF + t], wsT[(2 * k + 1) * SRF + t]);
    }

    const float* wrow = wsT + t * SRF;       // forward row (hidden unit t)
    const float h2 = 0.5f * DTV;
    float F0, F1;

    auto FORCE = [&](float sq0v, float sq1v) {
        qb0[t] = sq0v;
        qb1[t] = sq1v;
        __syncthreads();                                      // A
        // ---- forward: z_t = sum_f q_f * wsT[t][f] ----
        ull zA0 = 0, zA1 = 0, zB0 = 0, zB1 = 0;
#pragma unroll 5
        for (int f = 0; f < SRF; f += 4) {
            ulonglong2 w2 = *(const ulonglong2*)&wrow[f];
            ulonglong2 a2 = *(const ulonglong2*)&qb0[f];
            ulonglong2 b2 = *(const ulonglong2*)&qb1[f];
            fma2(zA0, w2.x, a2.x);
            fma2(zA1, w2.y, a2.y);
            fma2(zB0, w2.x, b2.x);
            fma2(zB1, w2.y, b2.y);
        }
#pragma unroll
        for (int m = 0; m < G / 4; m++) {
            ulonglong2 a2 = *(const ulonglong2*)&qb0[SRF + 4 * m];
            ulonglong2 b2 = *(const ulonglong2*)&qb1[SRF + 4 * m];
            fma2(zA0, wg[2 * m], a2.x);
            fma2(zA1, wg[2 * m + 1], a2.y);
            fma2(zB0, wg[2 * m], b2.x);
            fma2(zB1, wg[2 * m + 1], b2.y);
        }
        {
            float z0 = psum(zA0) + psum(zA1) + rb1;
            float z1 = psum(zB0) + psum(zB1) + rb1;
            float e0 = __expf(2.f * z0);
            float e1 = __expf(2.f * z1);
            float th0 = 1.f - 2.f / (e0 + 1.f);
            float th1 = 1.f - 2.f / (e1 + 1.f);
            ub0[t] = rw2 * (1.f - th0 * th0);
            ub1[t] = rw2 * (1.f - th1 * th1);
        }
        __syncthreads();                                      // B
        // ---- backward: F_t = sum_j wsT[j][t] * u_j  (t < SRF) ----
        ull fA0 = 0, fA1 = 0, fB0 = 0, fB1 = 0;
        float Fs0 = 0.f, Fs1 = 0.f;
        if (t < SRF) {
#pragma unroll 8
            for (int j = 0; j < RB; j += 4) {
                ulonglong2 u0 = *(const ulonglong2*)&ub0[j];
                ulonglong2 u1 = *(const ulonglong2*)&ub1[j];
                int k = j >> 1;
                fma2(fA0, rc[k], u0.x);
                fma2(fA1, rc[k + 1], u0.y);
                fma2(fB0, rc[k], u1.x);
                fma2(fB1, rc[k + 1], u1.y);
            }
#pragma unroll 8
            for (int j = RB; j < 256; j += 4) {
                float4 u0 = *(const float4*)&ub0[j];
                float4 u1 = *(const float4*)&ub1[j];
                float w0 = wsT[(j + 0) * SRF + t];
                float w1 = wsT[(j + 1) * SRF + t];
                float w2 = wsT[(j + 2) * SRF + t];
                float w3 = wsT[(j + 3) * SRF + t];
                Fs0 += w0 * u0.x + w1 * u0.y + w2 * u0.z + w3 * u0.w;
                Fs1 += w0 * u1.x + w1 * u1.y + w2 * u1.z + w3 * u1.w;
            }
        }
        // ---- backward rows f in [SRF,256): warp-cooperative from L2 ----
        {
            float4 ua0 = *(const float4*)&ub0[8 * lane];
            float4 ua1 = *(const float4*)&ub0[8 * lane + 4];
            float4 ubx = *(const float4*)&ub1[8 * lane];
            float4 uby = *(const float4*)&ub1[8 * lane + 4];
#pragma unroll
            for (int r = SRF + wid; r < 256; r += 8) {
                const float4* wr = (const float4*)(W1 + r * 256);
                float4 wa = __ldg(&wr[2 * lane]);
                float4 wb = __ldg(&wr[2 * lane + 1]);
                float v0 = dot4(wa, ua0) + dot4(wb, ua1);
                float v1 = dot4(wa, ubx) + dot4(wb, uby);
                v0 = warp_sum(v0);
                v1 = warp_sum(v1);
                if (lane == 0) { fb0[r - SRF] = v0; fb1[r - SRF] = v1; }
            }
        }
        __syncthreads();                                      // C
        if (t < SRF) {
            F0 = psum(fA0) + psum(fA1) + Fs0;
            F1 = psum(fB0) + psum(fB1) + Fs1;
        } else {
            F0 = fb0[t - SRF];
            F1 = fb1[t - SRF];
        }
    };

    for (int step = 0; step < STEPS; step++) {
        float aq0 = 0.f, ap0 = 0.f, aq1 = 0.f, ap1 = 0.f;
        float sq0 = q0, sp0 = p0, sq1 = q1, sp1 = p1;
        for (int stage = 0; stage < 4; stage++) {
            FORCE(sq0, sq1);
            float wk = (stage == 0 || stage == 3) ? 1.f : 2.f;
            aq0 += wk * sp0; ap0 -= wk * F0;
            aq1 += wk * sp1; ap1 -= wk * F1;
            if (stage < 3) {
                float c = (stage == 2) ? DTV : h2;
                float nsq0 = q0 + c * sp0, nsp0 = p0 - c * F0;
                float nsq1 = q1 + c * sp1, nsp1 = p1 - c * F1;
                sq0 = nsq0; sp0 = nsp0;
                sq1 = nsq1; sp1 = nsp1;
            }
        }
        const float d6 = DTV / 6.f;
        q0 += d6 * aq0; p0 += d6 * ap0;
        q1 += d6 * aq1; p1 += d6 * ap1;
    }

    ((float2*)out)[s0 * 256 + t]       = make_float2(q0, p0);
    ((float2*)out)[(s0 + 1) * 256 + t] = make_float2(q1, p1);
}

extern "C" void kernel_launch(void* const* d_in, const int* in_sizes, int n_in,
                              void* d_out, int out_size) {
    const float* x0 = (const float*)d_in[0];
    const float* W1 = (const float*)d_in[1];
    const float* b1 = (const float*)d_in[2];
    const float* W2 = (const float*)d_in[3];
    cudaFuncSetAttribute(hflow_kernel,
                         cudaFuncAttributeMaxDynamicSharedMemorySize, SMEM_BYTES);
    hflow_kernel<<<NCTA, NT, SMEM_BYTES>>>(x0, W1, b1, W2, (float*)d_out);
}

// round 4
// speedup vs baseline: 1.1726x; 1.0730x over previous
#include <cuda_runtime.h>

// HamiltonianFlow: 100 RK4 steps, software-pipelined: region r computes
// forward(stage r%4) CONCURRENTLY with backward(stage (r-1)%4), exploiting
// q_{s+1} = q0 + c*p_s needing only F_{s-1}. 401 regions, 2 barriers each.
//
// W1 transposed in SMEM: wsT[j][f], j in [0,256), f in [0,SRF). stride SRF=212
// (= 20 mod 32: conflict-free for row LDS.128 AND column scalar access).
// Backward j in [0,RB) register-cached; j in [RB,256) smem columns.
// f in [SRF,256) (G=44 rows): forward via regs, backward via L2 LDG + batched
// ILP shuffle reductions, loads issued at region top (latency hidden by fwd).

#define STEPS 100
#define DTV   0.01f
#define SRF   212
#define G     44
#define RB    64
#define NT    256
#define NCTA  128
#define NREG  (4 * STEPS + 1)

typedef unsigned long long ull;

#define WS_FLOATS (256 * SRF)
#define SMEM_FLOATS (WS_FLOATS + 1024 + 1024 + 128)
#define SMEM_BYTES (SMEM_FLOATS * 4)

__device__ __forceinline__ void fma2(ull& d, ull a, ull b) {
    asm("fma.rn.f32x2 %0, %1, %2, %0;" : "+l"(d) : "l"(a), "l"(b));
}
__device__ __forceinline__ ull pk2(float lo, float hi) {
    return (ull)__float_as_uint(lo) | ((ull)__float_as_uint(hi) << 32);
}
__device__ __forceinline__ float psum(ull v) {
    return __uint_as_float((unsigned)(v & 0xffffffffu)) +
           __uint_as_float((unsigned)(v >> 32));
}
__device__ __forceinline__ float dot4(float4 a, float4 b) {
    return a.x * b.x + a.y * b.y + a.z * b.z + a.w * b.w;
}

__global__ __launch_bounds__(NT, 1)
void hflow_kernel(const float* __restrict__ x0,
                  const float* __restrict__ W1,
                  const float* __restrict__ b1,
                  const float* __restrict__ W2,
                  float* __restrict__ out)
{
    extern __shared__ float sm[];
    float* wsT = sm;                        // [256][SRF]
    float* qb  = sm + WS_FLOATS;            // [2 buf][2 samp][256]
    float* ub  = qb + 1024;                 // [2 buf][2 samp][256]
    float* fb0 = ub + 1024;                 // [64]
    float* fb1 = fb0 + 64;                  // [64]

    const int t    = threadIdx.x;
    const int lane = t & 31;
    const int wid  = t >> 5;

    // ---- stage wsT (transposed) ----
    for (int idx = t; idx < SRF * 256; idx += NT) {
        int f = idx / 256, j = idx & 255;
        wsT[j * SRF + f] = W1[f * 256 + j];
    }
    // forward weights for f in [SRF,256)
    ull wg[G / 2];
#pragma unroll
    for (int k = 0; k < G / 2; k++)
        wg[k] = pk2(W1[(SRF + 2 * k) * 256 + t], W1[(SRF + 2 * k + 1) * 256 + t]);

    const float rb1 = b1[t];
    const float rw2 = W2[t];

    const int s0 = blockIdx.x * 2;
    float2 st0 = ((const float2*)x0)[s0 * 256 + t];
    float2 st1 = ((const float2*)x0)[(s0 + 1) * 256 + t];
    float q0[2], p0[2], Aq[2], Ap[2], pc[2];
    q0[0] = st0.x; p0[0] = st0.y;
    q0[1] = st1.x; p0[1] = st1.y;
    Ap[0] = Ap[1] = 0.f;

    // preload qbuf[0] with stage-0 q
    qb[t]       = q0[0];
    qb[256 + t] = q0[1];
    __syncthreads();                         // wsT + qb ready

    // register-cache backward j in [0,RB)
    ull rc[RB / 2];
    if (t < SRF) {
#pragma unroll
        for (int k = 0; k < RB / 2; k++)
            rc[k] = pk2(wsT[(2 * k) * SRF + t], wsT[(2 * k + 1) * SRF + t]);
    }

    const float* wrow = wsT + t * SRF;
    const float h2 = 0.5f * DTV;
    const float d6 = DTV / 6.f;

    const int nr = (wid < 4) ? 6 : 5;        // G rows per warp (44 = 8*5 + 4)

    for (int r = 0; r < NREG; r++) {
        const int par = r & 1;
        const float* qc = qb + par * 512;
        float*       qn = qb + (par ^ 1) * 512;
        float*       un = ub + par * 512;
        const float* uc = ub + (par ^ 1) * 512;
        const bool has_f = (r < NREG - 1);
        const bool has_b = (r > 0);

        // ---- G-row LDG issue (needs uc, ready at region entry) ----
        float4 wa[6], wb[6];
        if (has_b) {
#pragma unroll
            for (int k = 0; k < 6; k++) {
                if (k < nr) {
                    int row = (k < 5) ? (SRF + wid + 8 * k) : (252 + wid);
                    const float4* wr = (const float4*)(W1 + row * 256);
                    wa[k] = __ldg(&wr[2 * lane]);
                    wb[k] = __ldg(&wr[2 * lane + 1]);
                }
            }
        }

        // ---- forward: z_t = sum_f q_f * wsT[t][f] ----
        if (has_f) {
            ull zA0 = 0, zA1 = 0, zB0 = 0, zB1 = 0;
#pragma unroll 4
            for (int f = 0; f < SRF; f += 4) {
                ulonglong2 w2 = *(const ulonglong2*)&wrow[f];
                ulonglong2 a2 = *(const ulonglong2*)&qc[f];
                ulonglong2 b2 = *(const ulonglong2*)&qc[256 + f];
                fma2(zA0, w2.x, a2.x);
                fma2(zA1, w2.y, a2.y);
                fma2(zB0, w2.x, b2.x);
                fma2(zB1, w2.y, b2.y);
            }
#pragma unroll
            for (int m = 0; m < G / 4; m++) {
                ulonglong2 a2 = *(const ulonglong2*)&qc[SRF + 4 * m];
                ulonglong2 b2 = *(const ulonglong2*)&qc[256 + SRF + 4 * m];
                fma2(zA0, wg[2 * m], a2.x);
                fma2(zA1, wg[2 * m + 1], a2.y);
                fma2(zB0, wg[2 * m], b2.x);
                fma2(zB1, wg[2 * m + 1], b2.y);
            }
            float z0 = psum(zA0) + psum(zA1) + rb1;
            float z1 = psum(zB0) + psum(zB1) + rb1;
            float e0 = __expf(2.f * z0);
            float e1 = __expf(2.f * z1);
            float th0 = 1.f - 2.f / (e0 + 1.f);
            float th1 = 1.f - 2.f / (e1 + 1.f);
            un[t]       = rw2 * (1.f - th0 * th0);
            un[256 + t] = rw2 * (1.f - th1 * th1);
        }

        // ---- backward: F_t = sum_j wsT[j][t] * u_j  (stage r-1) ----
        float F[2];
        if (has_b) {
            ull fA0 = 0, fA1 = 0, fB0 = 0, fB1 = 0;
            float Fs0 = 0.f, Fs1 = 0.f;
            if (t < SRF) {
#pragma unroll
                for (int j = 0; j < RB; j += 4) {
                    ulonglong2 u0 = *(const ulonglong2*)&uc[j];
                    ulonglong2 u1 = *(const ulonglong2*)&uc[256 + j];
                    int k = j >> 1;
                    fma2(fA0, rc[k], u0.x);
                    fma2(fA1, rc[k + 1], u0.y);
                    fma2(fB0, rc[k], u1.x);
                    fma2(fB1, rc[k + 1], u1.y);
                }
#pragma unroll 6
                for (int j = RB; j < 256; j += 4) {
                    float4 u0 = *(const float4*)&uc[j];
                    float4 u1 = *(const float4*)&uc[256 + j];
                    float w0 = wsT[(j + 0) * SRF + t];
                    float w1 = wsT[(j + 1) * SRF + t];
                    float w2 = wsT[(j + 2) * SRF + t];
                    float w3 = wsT[(j + 3) * SRF + t];
                    Fs0 += w0 * u0.x + w1 * u0.y + w2 * u0.z + w3 * u0.w;
                    Fs1 += w0 * u1.x + w1 * u1.y + w2 * u1.z + w3 * u1.w;
                }
            }
            // ---- G rows: dots + batched ILP butterfly reduction ----
            {
                float4 ua0 = *(const float4*)&uc[8 * lane];
                float4 ua1 = *(const float4*)&uc[8 * lane + 4];
                float4 ubx = *(const float4*)&uc[256 + 8 * lane];
                float4 uby = *(const float4*)&uc[256 + 8 * lane + 4];
                float v0[6], v1[6];
#pragma unroll
                for (int k = 0; k < 6; k++) {
                    if (k < nr) {
                        v0[k] = dot4(wa[k], ua0) + dot4(wb[k], ua1);
                        v1[k] = dot4(wa[k], ubx) + dot4(wb[k], uby);
                    }
                }
#pragma unroll
                for (int m = 16; m >= 1; m >>= 1) {
#pragma unroll
                    for (int k = 0; k < 6; k++) {
                        if (k < nr) {
                            v0[k] += __shfl_xor_sync(0xffffffffu, v0[k], m);
                            v1[k] += __shfl_xor_sync(0xffffffffu, v1[k], m);
                        }
                    }
                }
                if (lane == 0) {
#pragma unroll
                    for (int k = 0; k < 6; k++) {
                        if (k < nr) {
                            int row = (k < 5) ? (SRF + wid + 8 * k) : (252 + wid);
                            fb0[row - SRF] = v0[k];
                            fb1[row - SRF] = v1[k];
                        }
                    }
                }
            }
            F[0] = psum(fA0) + psum(fA1) + Fs0;
            F[1] = psum(fB0) + psum(fB1) + Fs1;
        }

        __syncthreads();                              // B1: fb + un published

        if (has_b) {
            if (t >= SRF) {
                F[0] = fb0[t - SRF];
                F[1] = fb1[t - SRF];
            }
            const int sb = (r - 1) & 3;
            if (sb == 3) {
                // F_3 of previous step: finalize p, start new step
#pragma unroll
                for (int m = 0; m < 2; m++) {
                    Ap[m] += F[m];
                    p0[m] -= d6 * Ap[m];
                    Ap[m] = 0.f;
                    pc[m] = p0[m];
                    Aq[m] = pc[m];
                }
            } else {
                const float wb_ = (sb == 0) ? 1.f : 2.f;   // w[sb]
                const float cn  = (sb == 2) ? DTV : h2;    // c[sb+1]
                const float wn  = (sb == 2) ? 1.f : 2.f;   // w[sb+1]
#pragma unroll
                for (int m = 0; m < 2; m++) {
                    Ap[m] += wb_ * F[m];
                    pc[m] = p0[m] - cn * F[m];
                    Aq[m] += wn * pc[m];
                }
            }
        } else {
            // r == 0: stage 0, pc = p0
            pc[0] = p0[0]; Aq[0] = pc[0];
            pc[1] = p0[1]; Aq[1] = pc[1];
        }

        if (has_f) {
            const int sf = r & 3;
            if (sf == 3) {
                q0[0] += d6 * Aq[0];
                q0[1] += d6 * Aq[1];
                qn[t]       = q0[0];
                qn[256 + t] = q0[1];
            } else {
                const float cq = (sf == 2) ? DTV : h2;     // c[sf+1]
                qn[t]       = q0[0] + cq * pc[0];
                qn[256 + t] = q0[1] + cq * pc[1];
            }
        }

        __syncthreads();                              // B2: qn ready
    }

    ((float2*)out)[s0 * 256 + t]       = make_float2(q0[0], p0[0]);
    ((float2*)out)[(s0 + 1) * 256 + t] = make_float2(q0[1], p0[1]);
}

extern "C" void kernel_launch(void* const* d_in, const int* in_sizes, int n_in,
                              void* d_out, int out_size) {
    const float* x0 = (const float*)d_in[0];
    const float* W1 = (const float*)d_in[1];
    const float* b1 = (const float*)d_in[2];
    const float* W2 = (const float*)d_in[3];
    cudaFuncSetAttribute(hflow_kernel,
                         cudaFuncAttributeMaxDynamicSharedMemorySize, SMEM_BYTES);
    hflow_kernel<<<NCTA, NT, SMEM_BYTES>>>(x0, W1, b1, W2, (float*)d_out);
}